// round 10
// baseline (speedup 1.0000x reference)
#include <cuda_runtime.h>
#include <cuda_bf16.h>
#include <math.h>
#include <stdint.h>

#define K_ 256
#define D_ 256
#define P_ 40
#define C_ 32
#define NT 8192
#define KD (K_ * D_)

// ---------------- device scratch (no allocations allowed) ----------------
__device__ __align__(16) __nv_bfloat16 g_ehi[P_ * KD];  // [P][Ka][D] hi
__device__ __align__(16) __nv_bfloat16 g_elo[P_ * KD];  // [P][Ka][D] lo
__device__ __align__(16) __nv_bfloat16 g_thi[P_ * KD];  // [P][Kb][D] hi
__device__ __align__(16) __nv_bfloat16 g_tlo[P_ * KD];  // [P][Kb][D] lo
__device__ float g_tab[NT + 1];
__device__ float g_pw[P_];
__device__ __align__(16) float g_psc[P_ * K_ * K_];     // [p][a][b]
__device__ __align__(16) uint8_t g_msk[P_ * K_ * K_];   // [p][a][b]

// ---------------- kernel 1: fused prep (normpack | tab | pw) ---------------
// blocks 0..511: normpack (k = b>>1, sel = b&1), 320 threads
// blocks 512..537: tabulate g(x)
// block 538: positive_weight
__global__ void __launch_bounds__(320) prep_kernel(const float* __restrict__ enroll,
                                                   const float* __restrict__ test,
                                                   const float* __restrict__ pho,
                                                   const float* __restrict__ fc1w,
                                                   const float* __restrict__ fc1b,
                                                   const float* __restrict__ fc2w) {
    const int b = blockIdx.x;
    const int tid = threadIdx.x;

    if (b >= 512) {
        if (b == 538) {
            if (tid == 0) {
                float mn = pho[0], mx = pho[0];
                for (int p = 1; p < P_; p++) {
                    float v = pho[p];
                    mn = fminf(mn, v);
                    mx = fmaxf(mx, v);
                }
                float inv = 1.0f / (1e-6f + mx - mn);
                for (int p = 0; p < P_; p++) g_pw[p] = (pho[p] - mn) * inv;
            }
            return;
        }
        int i = (b - 512) * 320 + tid;
        if (i > NT) return;
        float x = -1.0f + (2.0f * (float)i) / (float)NT;
        float f = 0.0f;
#pragma unroll
        for (int c = 0; c < C_; c++) f += fc2w[c] * tanhf(x * fc1w[c] + fc1b[c]);
        g_tab[i] = tanhf(f * x);
        return;
    }

    __shared__ float s[256 * 41];        // [d][p] padded
    __shared__ float part[8 * 40];       // norm partials [g][p]
    __shared__ float sinv[P_];
    const int k = b >> 1;
    const int sel = b & 1;
    const float* in = (sel ? test : enroll) + (size_t)k * (D_ * P_);
    __nv_bfloat16* ohi = sel ? g_thi : g_ehi;
    __nv_bfloat16* olo = sel ? g_tlo : g_elo;

    // vectorized load: 2560 float4 per block, 8 per thread
    const float4* in4 = (const float4*)in;
    for (int i4 = tid; i4 < 2560; i4 += 320) {
        float4 v = in4[i4];
        int base = i4 * 4;
        int d = base / P_;
        int p = base - d * P_;
        s[d * 41 + p] = v.x;
        if (++p == P_) { p = 0; d++; }
        s[d * 41 + p] = v.y;
        if (++p == P_) { p = 0; d++; }
        s[d * 41 + p] = v.z;
        if (++p == P_) { p = 0; d++; }
        s[d * 41 + p] = v.w;
    }
    __syncthreads();

    // parallel norms: 40 p x 8 d-groups of 32
    {
        int p = tid % P_, g = tid / P_;
        int d0 = g * 32;
        float a0 = 0.f, a1 = 0.f;
#pragma unroll 16
        for (int d = 0; d < 32; d += 2) {
            float v0 = s[(d0 + d) * 41 + p];
            float v1 = s[(d0 + d + 1) * 41 + p];
            a0 += v0 * v0;
            a1 += v1 * v1;
        }
        part[g * P_ + p] = a0 + a1;
    }
    __syncthreads();
    if (tid < P_) {
        float a = 0.f;
#pragma unroll
        for (int g = 0; g < 8; g++) a += part[g * P_ + tid];
        float n = sqrtf(a);
        sinv[tid] = 1.0f / fmaxf(n, 1e-12f);
    }
    __syncthreads();

    // pack: 40 p x 128 d-pairs; per-warp fixed p, consecutive j -> coalesced
    for (int i = tid; i < P_ * 128; i += 320) {
        int p = i >> 7, j = i & 127;
        float inv = sinv[p];
        float v0 = s[(2 * j) * 41 + p] * inv;
        float v1 = s[(2 * j + 1) * 41 + p] * inv;
        __nv_bfloat16 h0 = __float2bfloat16(v0);
        __nv_bfloat16 h1 = __float2bfloat16(v1);
        __nv_bfloat16 lo0 = __float2bfloat16(v0 - __bfloat162float(h0));
        __nv_bfloat16 lo1 = __float2bfloat16(v1 - __bfloat162float(h1));
        unsigned hp = (unsigned)__bfloat16_as_ushort(h0) |
                      ((unsigned)__bfloat16_as_ushort(h1) << 16);
        unsigned lp = (unsigned)__bfloat16_as_ushort(lo0) |
                      ((unsigned)__bfloat16_as_ushort(lo1) << 16);
        size_t ob = (size_t)p * KD + (size_t)k * D_;
        ((unsigned*)(ohi + ob))[j] = hp;
        ((unsigned*)(olo + ob))[j] = lp;
    }
}

// ---------------- kernel 2: mma.sync bf16-split GEMM + LUT epilogue --------
// grid (4,4,40): 64x64 tile per CTA, 4 warps each 32x32.
// 12 K-chunks of 64 (3 hi/lo pairs x 4), 2-stage cp.async, fragment
// double-buffer over ks (ldmatrix for ks+1 overlaps MMAs of ks).

__device__ __forceinline__ uint32_t smem_u32(const void* p) {
    uint32_t a;
    asm("{ .reg .u64 t; cvta.to.shared.u64 t, %1; cvt.u32.u64 %0, t; }"
        : "=r"(a) : "l"(p));
    return a;
}

#define CP_ASYNC(dst, src) \
    asm volatile("cp.async.cg.shared.global [%0], [%1], 16;" \
                 :: "r"(dst), "l"(src) : "memory")
#define CP_COMMIT() asm volatile("cp.async.commit_group;" ::: "memory")
#define CP_WAIT(n) asm volatile("cp.async.wait_group %0;" :: "n"(n) : "memory")

#define LDM_X4(r0, r1, r2, r3, a) \
    asm volatile("ldmatrix.sync.aligned.m8n8.x4.shared.b16 {%0,%1,%2,%3}, [%4];" \
                 : "=r"(r0), "=r"(r1), "=r"(r2), "=r"(r3) : "r"(a))

#define MMA16816(d, av, b0v, b1v) \
    asm volatile("mma.sync.aligned.m16n8k16.row.col.f32.bf16.bf16.f32 " \
                 "{%0,%1,%2,%3}, {%4,%5,%6,%7}, {%8,%9}, {%0,%1,%2,%3};" \
                 : "+f"((d)[0]), "+f"((d)[1]), "+f"((d)[2]), "+f"((d)[3]) \
                 : "r"((av)[0]), "r"((av)[1]), "r"((av)[2]), "r"((av)[3]), \
                   "r"(b0v), "r"(b1v))

#define STAGE_SZ 16384

__global__ void __launch_bounds__(128) gemm_kernel() {
    extern __shared__ char dsm[];
    const int p = blockIdx.z;
    const int a0 = blockIdx.y * 64;
    const int b0 = blockIdx.x * 64;
    const int tid = threadIdx.x;
    const int wid = tid >> 5, lane = tid & 31;
    const int wm = (wid >> 1) * 32;   // warp m offset (0 or 32)
    const int wn = (wid & 1) * 32;    // warp n offset (0 or 32)
    const uint32_t sbase = smem_u32(dsm);

    const __nv_bfloat16* Ab[3] = {g_ehi + (size_t)p * KD + (size_t)a0 * D_,
                                  g_elo + (size_t)p * KD + (size_t)a0 * D_,
                                  g_ehi + (size_t)p * KD + (size_t)a0 * D_};
    const __nv_bfloat16* Bb[3] = {g_thi + (size_t)p * KD + (size_t)b0 * D_,
                                  g_thi + (size_t)p * KD + (size_t)b0 * D_,
                                  g_tlo + (size_t)p * KD + (size_t)b0 * D_};

    const int lr0 = tid >> 3;        // 0..15, base row
    const int lseg = tid & 7;        // 16B segment in 128B row

    const int arow0 = wm + (lane & 15);
    const int aseg0 = (lane >> 4);
    const int brow0 = wn + (lane & 7) + ((lane >> 4) << 3);
    const int bseg0 = (lane >> 3) & 1;

    float acc[2][4][4];
#pragma unroll
    for (int i = 0; i < 2; i++)
#pragma unroll
        for (int j = 0; j < 4; j++)
#pragma unroll
            for (int q = 0; q < 4; q++) acc[i][j][q] = 0.f;

    auto issue = [&](int c) {
        const int pr = c >> 2, co = c & 3;
        const char* As = (const char*)Ab[pr] + co * 128;
        const char* Bs = (const char*)Bb[pr] + co * 128;
        uint32_t st = sbase + (uint32_t)(c & 1) * STAGE_SZ;
#pragma unroll
        for (int j = 0; j < 4; j++) {
            int r = lr0 + j * 16;
            uint32_t sw = (uint32_t)(((lseg ^ (r & 7)) << 4));
            CP_ASYNC(st + (uint32_t)r * 128 + sw, As + (size_t)r * 512 + lseg * 16);
        }
#pragma unroll
        for (int j = 0; j < 4; j++) {
            int r = lr0 + j * 16;
            uint32_t sw = (uint32_t)(((lseg ^ (r & 7)) << 4));
            CP_ASYNC(st + 8192 + (uint32_t)r * 128 + sw, Bs + (size_t)r * 512 + lseg * 16);
        }
        CP_COMMIT();
    };

    issue(0);
    issue(1);

    uint32_t af[2][2][4], bfr[2][2][4];

    for (int c = 0; c < 12; c++) {
        if (c < 11) CP_WAIT(1); else CP_WAIT(0);
        __syncthreads();
        const uint32_t sA = sbase + (uint32_t)(c & 1) * STAGE_SZ;
        const uint32_t sB = sA + 8192;

        auto load_frags = [&](int ks, int buf) {
#pragma unroll
            for (int mt = 0; mt < 2; mt++) {
                int row = arow0 + mt * 16;
                int seg = aseg0 + ks * 2;
                uint32_t ad = sA + (uint32_t)row * 128 + (uint32_t)((seg ^ (row & 7)) << 4);
                LDM_X4(af[buf][mt][0], af[buf][mt][1], af[buf][mt][2], af[buf][mt][3], ad);
            }
#pragma unroll
            for (int np = 0; np < 2; np++) {
                int row = brow0 + np * 16;
                int seg = bseg0 + ks * 2;
                uint32_t bd = sB + (uint32_t)row * 128 + (uint32_t)((seg ^ (row & 7)) << 4);
                LDM_X4(bfr[buf][np][0], bfr[buf][np][1], bfr[buf][np][2], bfr[buf][np][3], bd);
            }
        };

        load_frags(0, 0);
#pragma unroll
        for (int ks = 0; ks < 4; ks++) {
            const int cur = ks & 1;
            if (ks < 3) load_frags(ks + 1, cur ^ 1);
#pragma unroll
            for (int mt = 0; mt < 2; mt++)
#pragma unroll
                for (int nt = 0; nt < 4; nt++)
                    MMA16816(acc[mt][nt], af[cur][mt],
                             bfr[cur][nt >> 1][(nt & 1) * 2],
                             bfr[cur][nt >> 1][(nt & 1) * 2 + 1]);
        }
        if (c + 2 < 12) {
            __syncthreads();
            issue(c + 2);
        }
    }

    // ---- epilogue: LUT + weight, direct stores ----
    const float pw = g_pw[p];
    float* psc = g_psc + (size_t)p * (K_ * K_);
    uint8_t* msk = g_msk + (size_t)p * (K_ * K_);
    const int rq = lane >> 2;          // 0..7
    const int cq = (lane & 3) << 1;    // 0,2,4,6

    auto lut = [&](float x) -> float {
        float xc = fminf(fmaxf(x, -1.0f), 1.0f);
        float tt = (xc + 1.0f) * ((float)NT * 0.5f);
        int i0 = (int)tt;
        i0 = min(i0, NT - 1);
        float fr = tt - (float)i0;
        float g0 = __ldg(&g_tab[i0]);
        float g1 = __ldg(&g_tab[i0 + 1]);
        return fmaf(fr, g1 - g0, g0) * pw;
    };

#pragma unroll
    for (int mt = 0; mt < 2; mt++)
#pragma unroll
        for (int nt = 0; nt < 4; nt++) {
            float* ac = acc[mt][nt];
            int ra = a0 + wm + mt * 16 + rq;
            int cb = b0 + wn + nt * 8 + cq;
            float2 v0 = make_float2(lut(ac[0]), lut(ac[1]));
            float2 v1 = make_float2(lut(ac[2]), lut(ac[3]));
            *(float2*)(psc + (size_t)ra * K_ + cb) = v0;
            *(float2*)(psc + (size_t)(ra + 8) * K_ + cb) = v1;
            uint16_t m0 = (uint16_t)((ac[0] != 0.f ? 1u : 0u) | (ac[1] != 0.f ? 0x100u : 0u));
            uint16_t m1 = (uint16_t)((ac[2] != 0.f ? 1u : 0u) | (ac[3] != 0.f ? 0x100u : 0u));
            *(uint16_t*)(msk + (size_t)ra * K_ + cb) = m0;
            *(uint16_t*)(msk + (size_t)(ra + 8) * K_ + cb) = m1;
        }
}

// ---------------- kernel 3: reduce over p + divide (vectorized x4) ---------
__global__ void __launch_bounds__(256) final_kernel(float* __restrict__ out) {
    __shared__ float spw[P_];
    if (threadIdx.x < P_) spw[threadIdx.x] = g_pw[threadIdx.x];
    __syncthreads();
    int i4 = (blockIdx.x * 256 + threadIdx.x) * 4;
    float s0 = 0.f, s1 = 0.f, s2 = 0.f, s3 = 0.f;
    float n0 = 0.f, n1 = 0.f, n2 = 0.f, n3 = 0.f;
#pragma unroll
    for (int p = 0; p < P_; p++) {
        float4 v = *(const float4*)&g_psc[(size_t)p * (K_ * K_) + i4];
        uchar4 m = *(const uchar4*)&g_msk[(size_t)p * (K_ * K_) + i4];
        float w = spw[p];
        s0 += v.x; s1 += v.y; s2 += v.z; s3 += v.w;
        if (m.x) n0 += w;
        if (m.y) n1 += w;
        if (m.z) n2 += w;
        if (m.w) n3 += w;
    }
    float4 o;
    o.x = s0 / (n0 + 1e-6f);
    o.y = s1 / (n1 + 1e-6f);
    o.z = s2 / (n2 + 1e-6f);
    o.w = s3 / (n3 + 1e-6f);
    *(float4*)&out[i4] = o;
}

// ---------------- launcher -------------------------------------------------
extern "C" void kernel_launch(void* const* d_in, const int* in_sizes, int n_in,
                              void* d_out, int out_size) {
    const float* enroll = (const float*)d_in[0];
    const float* test   = (const float*)d_in[1];
    const float* pho    = (const float*)d_in[2];
    const float* fc1w   = (const float*)d_in[3];
    const float* fc1b   = (const float*)d_in[4];
    const float* fc2w   = (const float*)d_in[5];
    float* out = (float*)d_out;

    const int gemm_smem = 2 * STAGE_SZ;
    cudaFuncSetAttribute(gemm_kernel, cudaFuncAttributeMaxDynamicSharedMemorySize,
                         gemm_smem);

    prep_kernel<<<539, 320>>>(enroll, test, pho, fc1w, fc1b, fc2w);
    gemm_kernel<<<dim3(4, 4, 40), 128, gemm_smem>>>();
    final_kernel<<<K_ * K_ / 1024, 256>>>(out);
}

// round 11
// speedup vs baseline: 1.0481x; 1.0481x over previous
#include <cuda_runtime.h>
#include <cuda_bf16.h>
#include <math.h>
#include <stdint.h>

#define K_ 256
#define D_ 256
#define P_ 40
#define C_ 32
#define NT 8192
#define KD (K_ * D_)

// ---------------- device scratch (no allocations allowed) ----------------
__device__ __align__(16) __nv_bfloat16 g_ehi[P_ * KD];  // [P][Ka][D] hi
__device__ __align__(16) __nv_bfloat16 g_elo[P_ * KD];  // [P][Ka][D] lo
__device__ __align__(16) __nv_bfloat16 g_thi[P_ * KD];  // [P][Kb][D] hi
__device__ __align__(16) __nv_bfloat16 g_tlo[P_ * KD];  // [P][Kb][D] lo
__device__ float g_tab[NT + 1];
__device__ float g_pw[P_];
__device__ __align__(16) float g_psc[P_ * K_ * K_];     // [p][a][b]
__device__ __align__(16) uint8_t g_msk[P_ * K_ * K_];   // [p][a][b]

// ---------------- kernel 1: fused prep (normpack | tab | pw) ---------------
// blocks 0..511: normpack (k = b>>1, sel = b&1)
// blocks 512..544: tabulate g(x)
// block 545: positive_weight
__global__ void __launch_bounds__(256) prep_kernel(const float* __restrict__ enroll,
                                                   const float* __restrict__ test,
                                                   const float* __restrict__ pho,
                                                   const float* __restrict__ fc1w,
                                                   const float* __restrict__ fc1b,
                                                   const float* __restrict__ fc2w) {
    const int b = blockIdx.x;
    const int tid = threadIdx.x;

    if (b >= 512) {
        if (b == 545) {
            if (tid == 0) {
                float mn = pho[0], mx = pho[0];
                for (int p = 1; p < P_; p++) {
                    float v = pho[p];
                    mn = fminf(mn, v);
                    mx = fmaxf(mx, v);
                }
                float inv = 1.0f / (1e-6f + mx - mn);
                for (int p = 0; p < P_; p++) g_pw[p] = (pho[p] - mn) * inv;
            }
            return;
        }
        int i = (b - 512) * 256 + tid;
        if (i > NT) return;
        float x = -1.0f + (2.0f * (float)i) / (float)NT;
        float f = 0.0f;
#pragma unroll
        for (int c = 0; c < C_; c++) f += fc2w[c] * tanhf(x * fc1w[c] + fc1b[c]);
        g_tab[i] = tanhf(f * x);
        return;
    }

    __shared__ float s[256 * 41];        // [d][p] padded (stride 41)
    __shared__ float part[8 * 40];       // norm partials [warp][p]
    __shared__ float sinv[P_];
    const int k = b >> 1;
    const int sel = b & 1;
    const float* in = (sel ? test : enroll) + (size_t)k * (D_ * P_);
    __nv_bfloat16* ohi = sel ? g_thi : g_ehi;
    __nv_bfloat16* olo = sel ? g_tlo : g_elo;

    // ---- phase 1: float4 loads, carry-free indexing ----
    // element base = 4*i4; 4*i4 mod 40 = 4*(i4 mod 10) -> p0 multiple of 4,
    // quad never crosses the p boundary; one d per quad.
    {
        const float4* in4 = (const float4*)in;
        int m = tid % 10;        // i4 mod 10
        int d = tid / 10;        // i4 / 10
#pragma unroll
        for (int it = 0; it < 10; it++) {
            int i4 = tid + it * 256;
            float4 v = in4[i4];
            float* dst = &s[d * 41 + 4 * m];
            dst[0] = v.x;
            dst[1] = v.y;
            dst[2] = v.z;
            dst[3] = v.w;
            m += 6;
            d += 25;
            if (m >= 10) { m -= 10; d += 1; }
        }
    }
    __syncthreads();

    // ---- phase 2: norms. warp w owns d in [w*32, w*32+32);
    // lane l accumulates p=l (and p=32+l for l<8). stride-1, conflict-free.
    {
        const int w = tid >> 5, l = tid & 31;
        const int d0 = w * 32;
        float a1 = 0.f, a2 = 0.f;
#pragma unroll 8
        for (int d = 0; d < 32; d++) {
            float v1 = s[(d0 + d) * 41 + l];
            a1 += v1 * v1;
            if (l < 8) {
                float v2 = s[(d0 + d) * 41 + 32 + l];
                a2 += v2 * v2;
            }
        }
        part[w * P_ + l] = a1;
        if (l < 8) part[w * P_ + 32 + l] = a2;
    }
    __syncthreads();
    if (tid < P_) {
        float a = 0.f;
#pragma unroll
        for (int g = 0; g < 8; g++) a += part[g * P_ + tid];
        float n = sqrtf(a);
        sinv[tid] = 1.0f / fmaxf(n, 1e-12f);
    }
    __syncthreads();

    // ---- phase 3: pack. 40 p x 128 d-pairs; fixed p per warp -> coalesced.
    for (int i = tid; i < P_ * 128; i += 256) {
        int p = i >> 7, j = i & 127;
        float inv = sinv[p];
        float v0 = s[(2 * j) * 41 + p] * inv;
        float v1 = s[(2 * j + 1) * 41 + p] * inv;
        __nv_bfloat16 h0 = __float2bfloat16(v0);
        __nv_bfloat16 h1 = __float2bfloat16(v1);
        __nv_bfloat16 lo0 = __float2bfloat16(v0 - __bfloat162float(h0));
        __nv_bfloat16 lo1 = __float2bfloat16(v1 - __bfloat162float(h1));
        unsigned hp = (unsigned)__bfloat16_as_ushort(h0) |
                      ((unsigned)__bfloat16_as_ushort(h1) << 16);
        unsigned lp = (unsigned)__bfloat16_as_ushort(lo0) |
                      ((unsigned)__bfloat16_as_ushort(lo1) << 16);
        size_t ob = (size_t)p * KD + (size_t)k * D_;
        ((unsigned*)(ohi + ob))[j] = hp;
        ((unsigned*)(olo + ob))[j] = lp;
    }
}

// ---------------- kernel 2: mma.sync bf16-split GEMM + LUT epilogue --------
// grid (4,4,40): 64x64 tile per CTA, 4 warps each 32x32.
// 12 K-chunks of 64 (3 hi/lo pairs x 4), 2-stage cp.async, fragment
// double-buffer over ks (ldmatrix for ks+1 overlaps MMAs of ks).

__device__ __forceinline__ uint32_t smem_u32(const void* p) {
    uint32_t a;
    asm("{ .reg .u64 t; cvta.to.shared.u64 t, %1; cvt.u32.u64 %0, t; }"
        : "=r"(a) : "l"(p));
    return a;
}

#define CP_ASYNC(dst, src) \
    asm volatile("cp.async.cg.shared.global [%0], [%1], 16;" \
                 :: "r"(dst), "l"(src) : "memory")
#define CP_COMMIT() asm volatile("cp.async.commit_group;" ::: "memory")
#define CP_WAIT(n) asm volatile("cp.async.wait_group %0;" :: "n"(n) : "memory")

#define LDM_X4(r0, r1, r2, r3, a) \
    asm volatile("ldmatrix.sync.aligned.m8n8.x4.shared.b16 {%0,%1,%2,%3}, [%4];" \
                 : "=r"(r0), "=r"(r1), "=r"(r2), "=r"(r3) : "r"(a))

#define MMA16816(d, av, b0v, b1v) \
    asm volatile("mma.sync.aligned.m16n8k16.row.col.f32.bf16.bf16.f32 " \
                 "{%0,%1,%2,%3}, {%4,%5,%6,%7}, {%8,%9}, {%0,%1,%2,%3};" \
                 : "+f"((d)[0]), "+f"((d)[1]), "+f"((d)[2]), "+f"((d)[3]) \
                 : "r"((av)[0]), "r"((av)[1]), "r"((av)[2]), "r"((av)[3]), \
                   "r"(b0v), "r"(b1v))

#define STAGE_SZ 16384

__global__ void __launch_bounds__(128) gemm_kernel() {
    extern __shared__ char dsm[];
    const int p = blockIdx.z;
    const int a0 = blockIdx.y * 64;
    const int b0 = blockIdx.x * 64;
    const int tid = threadIdx.x;
    const int wid = tid >> 5, lane = tid & 31;
    const int wm = (wid >> 1) * 32;   // warp m offset (0 or 32)
    const int wn = (wid & 1) * 32;    // warp n offset (0 or 32)
    const uint32_t sbase = smem_u32(dsm);

    const __nv_bfloat16* Ab[3] = {g_ehi + (size_t)p * KD + (size_t)a0 * D_,
                                  g_elo + (size_t)p * KD + (size_t)a0 * D_,
                                  g_ehi + (size_t)p * KD + (size_t)a0 * D_};
    const __nv_bfloat16* Bb[3] = {g_thi + (size_t)p * KD + (size_t)b0 * D_,
                                  g_thi + (size_t)p * KD + (size_t)b0 * D_,
                                  g_tlo + (size_t)p * KD + (size_t)b0 * D_};

    const int lr0 = tid >> 3;        // 0..15, base row
    const int lseg = tid & 7;        // 16B segment in 128B row

    const int arow0 = wm + (lane & 15);
    const int aseg0 = (lane >> 4);
    const int brow0 = wn + (lane & 7) + ((lane >> 4) << 3);
    const int bseg0 = (lane >> 3) & 1;

    float acc[2][4][4];
#pragma unroll
    for (int i = 0; i < 2; i++)
#pragma unroll
        for (int j = 0; j < 4; j++)
#pragma unroll
            for (int q = 0; q < 4; q++) acc[i][j][q] = 0.f;

    auto issue = [&](int c) {
        const int pr = c >> 2, co = c & 3;
        const char* As = (const char*)Ab[pr] + co * 128;
        const char* Bs = (const char*)Bb[pr] + co * 128;
        uint32_t st = sbase + (uint32_t)(c & 1) * STAGE_SZ;
#pragma unroll
        for (int j = 0; j < 4; j++) {
            int r = lr0 + j * 16;
            uint32_t sw = (uint32_t)(((lseg ^ (r & 7)) << 4));
            CP_ASYNC(st + (uint32_t)r * 128 + sw, As + (size_t)r * 512 + lseg * 16);
        }
#pragma unroll
        for (int j = 0; j < 4; j++) {
            int r = lr0 + j * 16;
            uint32_t sw = (uint32_t)(((lseg ^ (r & 7)) << 4));
            CP_ASYNC(st + 8192 + (uint32_t)r * 128 + sw, Bs + (size_t)r * 512 + lseg * 16);
        }
        CP_COMMIT();
    };

    issue(0);
    issue(1);

    uint32_t af[2][2][4], bfr[2][2][4];

    for (int c = 0; c < 12; c++) {
        if (c < 11) CP_WAIT(1); else CP_WAIT(0);
        __syncthreads();
        const uint32_t sA = sbase + (uint32_t)(c & 1) * STAGE_SZ;
        const uint32_t sB = sA + 8192;

        auto load_frags = [&](int ks, int buf) {
#pragma unroll
            for (int mt = 0; mt < 2; mt++) {
                int row = arow0 + mt * 16;
                int seg = aseg0 + ks * 2;
                uint32_t ad = sA + (uint32_t)row * 128 + (uint32_t)((seg ^ (row & 7)) << 4);
                LDM_X4(af[buf][mt][0], af[buf][mt][1], af[buf][mt][2], af[buf][mt][3], ad);
            }
#pragma unroll
            for (int np = 0; np < 2; np++) {
                int row = brow0 + np * 16;
                int seg = bseg0 + ks * 2;
                uint32_t bd = sB + (uint32_t)row * 128 + (uint32_t)((seg ^ (row & 7)) << 4);
                LDM_X4(bfr[buf][np][0], bfr[buf][np][1], bfr[buf][np][2], bfr[buf][np][3], bd);
            }
        };

        load_frags(0, 0);
#pragma unroll
        for (int ks = 0; ks < 4; ks++) {
            const int cur = ks & 1;
            if (ks < 3) load_frags(ks + 1, cur ^ 1);
#pragma unroll
            for (int mt = 0; mt < 2; mt++)
#pragma unroll
                for (int nt = 0; nt < 4; nt++)
                    MMA16816(acc[mt][nt], af[cur][mt],
                             bfr[cur][nt >> 1][(nt & 1) * 2],
                             bfr[cur][nt >> 1][(nt & 1) * 2 + 1]);
        }
        if (c + 2 < 12) {
            __syncthreads();
            issue(c + 2);
        }
    }

    // ---- epilogue: LUT + weight, direct stores ----
    const float pw = g_pw[p];
    float* psc = g_psc + (size_t)p * (K_ * K_);
    uint8_t* msk = g_msk + (size_t)p * (K_ * K_);
    const int rq = lane >> 2;          // 0..7
    const int cq = (lane & 3) << 1;    // 0,2,4,6

    auto lut = [&](float x) -> float {
        float xc = fminf(fmaxf(x, -1.0f), 1.0f);
        float tt = (xc + 1.0f) * ((float)NT * 0.5f);
        int i0 = (int)tt;
        i0 = min(i0, NT - 1);
        float fr = tt - (float)i0;
        float g0 = __ldg(&g_tab[i0]);
        float g1 = __ldg(&g_tab[i0 + 1]);
        return fmaf(fr, g1 - g0, g0) * pw;
    };

#pragma unroll
    for (int mt = 0; mt < 2; mt++)
#pragma unroll
        for (int nt = 0; nt < 4; nt++) {
            float* ac = acc[mt][nt];
            int ra = a0 + wm + mt * 16 + rq;
            int cb = b0 + wn + nt * 8 + cq;
            float2 v0 = make_float2(lut(ac[0]), lut(ac[1]));
            float2 v1 = make_float2(lut(ac[2]), lut(ac[3]));
            *(float2*)(psc + (size_t)ra * K_ + cb) = v0;
            *(float2*)(psc + (size_t)(ra + 8) * K_ + cb) = v1;
            uint16_t m0 = (uint16_t)((ac[0] != 0.f ? 1u : 0u) | (ac[1] != 0.f ? 0x100u : 0u));
            uint16_t m1 = (uint16_t)((ac[2] != 0.f ? 1u : 0u) | (ac[3] != 0.f ? 0x100u : 0u));
            *(uint16_t*)(msk + (size_t)ra * K_ + cb) = m0;
            *(uint16_t*)(msk + (size_t)(ra + 8) * K_ + cb) = m1;
        }
}

// ---------------- kernel 3: reduce over p + divide (vectorized x4) ---------
__global__ void __launch_bounds__(256) final_kernel(float* __restrict__ out) {
    __shared__ float spw[P_];
    if (threadIdx.x < P_) spw[threadIdx.x] = g_pw[threadIdx.x];
    __syncthreads();
    int i4 = (blockIdx.x * 256 + threadIdx.x) * 4;
    float s0 = 0.f, s1 = 0.f, s2 = 0.f, s3 = 0.f;
    float n0 = 0.f, n1 = 0.f, n2 = 0.f, n3 = 0.f;
#pragma unroll
    for (int p = 0; p < P_; p++) {
        float4 v = *(const float4*)&g_psc[(size_t)p * (K_ * K_) + i4];
        uchar4 m = *(const uchar4*)&g_msk[(size_t)p * (K_ * K_) + i4];
        float w = spw[p];
        s0 += v.x; s1 += v.y; s2 += v.z; s3 += v.w;
        if (m.x) n0 += w;
        if (m.y) n1 += w;
        if (m.z) n2 += w;
        if (m.w) n3 += w;
    }
    float4 o;
    o.x = s0 / (n0 + 1e-6f);
    o.y = s1 / (n1 + 1e-6f);
    o.z = s2 / (n2 + 1e-6f);
    o.w = s3 / (n3 + 1e-6f);
    *(float4*)&out[i4] = o;
}

// ---------------- launcher -------------------------------------------------
extern "C" void kernel_launch(void* const* d_in, const int* in_sizes, int n_in,
                              void* d_out, int out_size) {
    const float* enroll = (const float*)d_in[0];
    const float* test   = (const float*)d_in[1];
    const float* pho    = (const float*)d_in[2];
    const float* fc1w   = (const float*)d_in[3];
    const float* fc1b   = (const float*)d_in[4];
    const float* fc2w   = (const float*)d_in[5];
    float* out = (float*)d_out;

    const int gemm_smem = 2 * STAGE_SZ;
    cudaFuncSetAttribute(gemm_kernel, cudaFuncAttributeMaxDynamicSharedMemorySize,
                         gemm_smem);

    prep_kernel<<<546, 256>>>(enroll, test, pho, fc1w, fc1b, fc2w);
    gemm_kernel<<<dim3(4, 4, 40), 128, gemm_smem>>>();
    final_kernel<<<K_ * K_ / 1024, 256>>>(out);
}